// round 1
// baseline (speedup 1.0000x reference)
#include <cuda_runtime.h>
#include <math.h>

#define BB 8
#define NN 4096
#define DEG 16
#define UU 128
#define EE (NN*DEG)
#define MM (BB*NN)
#define K2 256
#define DEPTH 3

// log10(17) in fp32
#define SCALE_C 1.2304489f

// ------------------- device scratch (no allocations allowed) -------------------
__device__ float g_x[(size_t)MM * UU];          // 16.8 MB node features (ping buffer)
__device__ float g_sagg[(size_t)MM * K2];       // 33.5 MB [ssum | smax]
__device__ float g_wcat[DEPTH * K2 * UU];       // folded weights
__device__ float g_bn_a[DEPTH * UU];
__device__ float g_bn_d[DEPTH * UU];
__device__ float g_gm[BB * UU];
__device__ float g_h1[BB * UU];

// ------------------- weight folding -------------------
__global__ void fold_w_kernel(const float* __restrict__ W) {
    int t = blockIdx.x * blockDim.x + threadIdx.x;
    if (t >= DEPTH * K2 * UU) return;
    int j = t & 127;
    int k = (t >> 7) & 255;
    int l = t >> 15;
    const float c = SCALE_C;
    const float* Wl = W + (size_t)l * 1152 * UU;
    float v;
    if (k < 128) {
        float w0 = Wl[(0 * 128 + k) * UU + j];
        float w1 = Wl[(1 * 128 + k) * UU + j];
        float w2 = Wl[(2 * 128 + k) * UU + j];
        float w6 = Wl[(6 * 128 + k) * UU + j];
        float w7 = Wl[(7 * 128 + k) * UU + j];
        float w8 = Wl[(8 * 128 + k) * UU + j];
        v = (w0 + c * (w1 + w2)) * 0.0625f + w6 + c * (w7 + w8);
    } else {
        int kk = k - 128;
        float w3 = Wl[(3 * 128 + kk) * UU + j];
        float w4 = Wl[(4 * 128 + kk) * UU + j];
        float w5 = Wl[(5 * 128 + kk) * UU + j];
        v = w3 + c * (w4 + w5);
    }
    g_wcat[t] = v;
}

__global__ void fold_bn_kernel(const float* __restrict__ gamma, const float* __restrict__ beta,
                               const float* __restrict__ mm, const float* __restrict__ mv) {
    int t = blockIdx.x * blockDim.x + threadIdx.x;
    if (t >= DEPTH * UU) return;
    float a = gamma[t] * rsqrtf(mv[t] + 1e-3f);
    g_bn_a[t] = a;
    g_bn_d[t] = beta[t] - mm[t] * a;
}

// ------------------- aggregation: one warp per node -------------------
__global__ void agg_kernel(const float* __restrict__ xin, const int* __restrict__ ei) {
    const float* x = xin ? xin : g_x;
    int gw = (blockIdx.x * blockDim.x + threadIdx.x) >> 5;
    int lane = threadIdx.x & 31;
    if (gw >= MM) return;
    int b = gw >> 12;
    int nd = gw & (NN - 1);
    const int* ep = ei + 2 * ((size_t)b * EE + (size_t)nd * DEG);
    int myd = (lane < DEG) ? ep[2 * lane + 1] : 0;
    const float* xb = x + (size_t)b * NN * UU;
    float4 s = make_float4(0.f, 0.f, 0.f, 0.f);
    float ninf = __int_as_float(0xff800000);
    float4 mx = make_float4(ninf, ninf, ninf, ninf);
    #pragma unroll
    for (int e = 0; e < DEG; e++) {
        int d = __shfl_sync(0xffffffffu, myd, e);
        float4 v = __ldg((const float4*)(xb + (size_t)d * UU + lane * 4));
        s.x += v.x; s.y += v.y; s.z += v.z; s.w += v.w;
        mx.x = fmaxf(mx.x, v.x); mx.y = fmaxf(mx.y, v.y);
        mx.z = fmaxf(mx.z, v.z); mx.w = fmaxf(mx.w, v.w);
    }
    float* o = g_sagg + (size_t)gw * K2 + lane * 4;
    *(float4*)o = s;
    *(float4*)(o + UU) = mx;
}

// ------------------- packed f32x2 helpers -------------------
__device__ __forceinline__ unsigned long long ffma2(unsigned long long a, unsigned long long b,
                                                    unsigned long long c) {
    unsigned long long d;
    asm("fma.rn.f32x2 %0, %1, %2, %3;" : "=l"(d) : "l"(a), "l"(b), "l"(c));
    return d;
}

// ------------------- GEMM + fused epilogue -------------------
// C[m][j] = relu( sum_k A[m][k]*Wc[k][j] + bias[j] ) * av[j] + dv[j]
// A = g_sagg [M, 256], Wc = g_wcat[l] [256, 128], C = g_x [M, 128]
__global__ __launch_bounds__(256, 2) void gemm_epi_kernel(int l, const float* __restrict__ bias) {
    __shared__ __align__(16) float As2[8][256];   // k-major, each A value duplicated (v,v)
    __shared__ __align__(16) float Bs[8][128];
    const float* A = g_sagg;
    const float* Bw = g_wcat + (size_t)l * K2 * UU;
    int tid = threadIdx.x;
    int m0 = blockIdx.x * 128;
    int tm = (tid >> 4) << 3;   // 0..120
    int tn = (tid & 15) << 3;   // 0..120

    unsigned long long acc[8][4];
    #pragma unroll
    for (int i = 0; i < 8; i++)
        #pragma unroll
        for (int j = 0; j < 4; j++) acc[i][j] = 0ull;

    int arow = tid >> 1;          // 0..127
    int acol = (tid & 1) << 2;    // 0 or 4
    int brow = tid >> 5;          // 0..7
    int bcol = (tid & 31) << 2;   // 0..124
    const float* Ag = A + (size_t)(m0 + arow) * K2 + acol;
    const float* Bg = Bw + brow * UU + bcol;

    for (int k0 = 0; k0 < K2; k0 += 8) {
        float4 a4 = *(const float4*)(Ag + k0);
        float4 b4 = *(const float4*)(Bg + (size_t)k0 * UU);
        __syncthreads();
        As2[acol + 0][2 * arow] = a4.x; As2[acol + 0][2 * arow + 1] = a4.x;
        As2[acol + 1][2 * arow] = a4.y; As2[acol + 1][2 * arow + 1] = a4.y;
        As2[acol + 2][2 * arow] = a4.z; As2[acol + 2][2 * arow + 1] = a4.z;
        As2[acol + 3][2 * arow] = a4.w; As2[acol + 3][2 * arow + 1] = a4.w;
        *(float4*)&Bs[brow][bcol] = b4;
        __syncthreads();
        #pragma unroll
        for (int k = 0; k < 8; k++) {
            unsigned long long ra[8], rb[4];
            const unsigned long long* ap = (const unsigned long long*)&As2[k][2 * tm];
            const unsigned long long* bp = (const unsigned long long*)&Bs[k][tn];
            #pragma unroll
            for (int i = 0; i < 8; i++) ra[i] = ap[i];
            #pragma unroll
            for (int j = 0; j < 4; j++) rb[j] = bp[j];
            #pragma unroll
            for (int i = 0; i < 8; i++)
                #pragma unroll
                for (int j = 0; j < 4; j++)
                    acc[i][j] = ffma2(ra[i], rb[j], acc[i][j]);
        }
    }

    const float* av = g_bn_a + l * UU;
    const float* dv = g_bn_d + l * UU;
    float bia[8], avr[8], dvr[8];
    #pragma unroll
    for (int j = 0; j < 8; j++) {
        bia[j] = bias[tn + j];
        avr[j] = av[tn + j];
        dvr[j] = dv[tn + j];
    }
    #pragma unroll
    for (int i = 0; i < 8; i++) {
        float outv[8];
        #pragma unroll
        for (int j = 0; j < 4; j++) {
            float lo, hi;
            asm("mov.b64 {%0,%1}, %2;" : "=f"(lo), "=f"(hi) : "l"(acc[i][j]));
            outv[2 * j]     = fmaxf(lo + bia[2 * j], 0.f)     * avr[2 * j]     + dvr[2 * j];
            outv[2 * j + 1] = fmaxf(hi + bia[2 * j + 1], 0.f) * avr[2 * j + 1] + dvr[2 * j + 1];
        }
        float4* dst = (float4*)(g_x + (size_t)(m0 + tm + i) * UU + tn);
        dst[0] = make_float4(outv[0], outv[1], outv[2], outv[3]);
        dst[1] = make_float4(outv[4], outv[5], outv[6], outv[7]);
    }
}

// ------------------- readout mean over nodes -------------------
__global__ void readout_kernel() {
    int b = blockIdx.x, j = threadIdx.x;
    const float* xb = g_x + (size_t)b * NN * UU;
    float s0 = 0.f, s1 = 0.f, s2 = 0.f, s3 = 0.f;
    for (int n = 0; n < NN; n += 4) {
        s0 += xb[(size_t)n * UU + j];
        s1 += xb[(size_t)(n + 1) * UU + j];
        s2 += xb[(size_t)(n + 2) * UU + j];
        s3 += xb[(size_t)(n + 3) * UU + j];
    }
    g_gm[b * UU + j] = (s0 + s1 + s2 + s3) * (1.f / NN);
}

__global__ void mlp1_kernel(const float* __restrict__ Wp1, const float* __restrict__ bp1) {
    __shared__ float gs[UU];
    int b = blockIdx.x, j = threadIdx.x;
    gs[j] = g_gm[b * UU + j];
    __syncthreads();
    float acc = bp1[j];
    #pragma unroll 8
    for (int k = 0; k < UU; k++) acc += gs[k] * Wp1[k * UU + j];
    g_h1[b * UU + j] = fmaxf(acc, 0.f);
}

__global__ void mlp2_kernel(const float* __restrict__ Wp2, const float* __restrict__ bp2,
                            float* __restrict__ out) {
    __shared__ float gs[UU];
    int b = blockIdx.x, j = threadIdx.x;  // 64 threads
    gs[j] = g_h1[b * UU + j];
    gs[j + 64] = g_h1[b * UU + j + 64];
    __syncthreads();
    float acc = bp2[j];
    #pragma unroll 8
    for (int k = 0; k < UU; k++) acc += gs[k] * Wp2[k * 64 + j];
    out[b * 64 + j] = fmaxf(acc, 0.f);
}

// ------------------- launch -------------------
extern "C" void kernel_launch(void* const* d_in, const int* in_sizes, int n_in,
                              void* d_out, int out_size) {
    const float* x0    = (const float*)d_in[0];
    const int*   ei    = (const int*)d_in[1];
    const float* W     = (const float*)d_in[2];
    const float* bvec  = (const float*)d_in[3];
    const float* gamma = (const float*)d_in[4];
    const float* beta  = (const float*)d_in[5];
    const float* mmean = (const float*)d_in[6];
    const float* mvar  = (const float*)d_in[7];
    const float* Wp1   = (const float*)d_in[8];
    const float* bp1   = (const float*)d_in[9];
    const float* Wp2   = (const float*)d_in[10];
    const float* bp2   = (const float*)d_in[11];

    fold_w_kernel<<<96, 1024>>>(W);
    fold_bn_kernel<<<3, 128>>>(gamma, beta, mmean, mvar);

    for (int l = 0; l < DEPTH; l++) {
        agg_kernel<<<MM / 8, 256>>>(l == 0 ? x0 : (const float*)nullptr, ei);
        gemm_epi_kernel<<<MM / 128, 256>>>(l, bvec + l * UU);
    }

    readout_kernel<<<BB, 128>>>();
    mlp1_kernel<<<BB, 128>>>(Wp1, bp1);
    mlp2_kernel<<<BB, 64>>>(Wp2, bp2, (float*)d_out);
}

// round 3
// speedup vs baseline: 1.6817x; 1.6817x over previous
#include <cuda_runtime.h>
#include <cuda_bf16.h>
#include <math.h>
#include <stdint.h>

#define BB 8
#define NN 4096
#define DEG 16
#define UU 128
#define EE (NN*DEG)
#define MM (BB*NN)
#define K2 256
#define DEPTH 3
#define SCALE_C 1.2304489f

// ------------------- device scratch -------------------
__device__ float g_x[(size_t)MM * UU];                 // node features ping buffer (fp32)
__device__ __nv_bfloat16 g_ahi[(size_t)MM * K2];       // bf16-hi of [ssum|smax], [m][k]
__device__ __nv_bfloat16 g_alo[(size_t)MM * K2];       // bf16-lo residual
__device__ __nv_bfloat16 g_bhi[DEPTH * UU * K2];       // folded W, [n][k] K-major, hi
__device__ __nv_bfloat16 g_blo[DEPTH * UU * K2];
__device__ float g_bn_a[DEPTH * UU];
__device__ float g_bn_d[DEPTH * UU];
__device__ float g_gm[BB * UU];
__device__ float g_h1[BB * UU];

// ------------------- helpers -------------------
__device__ __forceinline__ uint32_t smem_u32(const void* p) {
    uint32_t a;
    asm("{ .reg .u64 t; cvta.to.shared.u64 t, %1; cvt.u32.u64 %0, t; }" : "=r"(a) : "l"(p));
    return a;
}
__device__ __forceinline__ void cp16(uint32_t dst, const void* src) {
    asm volatile("cp.async.cg.shared.global [%0], [%1], 16;" :: "r"(dst), "l"(src) : "memory");
}
__device__ __forceinline__ void cp_commit() {
    asm volatile("cp.async.commit_group;" ::: "memory");
}
__device__ __forceinline__ void ldmx4(uint32_t* r, uint32_t addr) {
    asm volatile("ldmatrix.sync.aligned.m8n8.x4.shared.b16 {%0,%1,%2,%3}, [%4];"
                 : "=r"(r[0]), "=r"(r[1]), "=r"(r[2]), "=r"(r[3]) : "r"(addr));
}
__device__ __forceinline__ void mma_bf16(float* c, const uint32_t* a, uint32_t b0, uint32_t b1) {
    asm volatile("mma.sync.aligned.m16n8k16.row.col.f32.bf16.bf16.f32 "
                 "{%0,%1,%2,%3}, {%4,%5,%6,%7}, {%8,%9}, {%0,%1,%2,%3};"
                 : "+f"(c[0]), "+f"(c[1]), "+f"(c[2]), "+f"(c[3])
                 : "r"(a[0]), "r"(a[1]), "r"(a[2]), "r"(a[3]), "r"(b0), "r"(b1));
}
#define SWZ(off) ((off) ^ (((off) >> 3) & 0x70))

// ------------------- weight folding (bf16 split, K-major [n][k]) -------------------
__global__ void fold_w_kernel(const float* __restrict__ W) {
    int t = blockIdx.x * blockDim.x + threadIdx.x;
    if (t >= DEPTH * K2 * UU) return;
    int j = t & 127;          // output feature n
    int k = (t >> 7) & 255;   // k index
    int l = t >> 15;
    const float c = SCALE_C;
    const float* Wl = W + (size_t)l * 1152 * UU;
    float v;
    if (k < 128) {
        float w0 = Wl[(0 * 128 + k) * UU + j];
        float w1 = Wl[(1 * 128 + k) * UU + j];
        float w2 = Wl[(2 * 128 + k) * UU + j];
        float w6 = Wl[(6 * 128 + k) * UU + j];
        float w7 = Wl[(7 * 128 + k) * UU + j];
        float w8 = Wl[(8 * 128 + k) * UU + j];
        v = (w0 + c * (w1 + w2)) * 0.0625f + w6 + c * (w7 + w8);
    } else {
        int kk = k - 128;
        float w3 = Wl[(3 * 128 + kk) * UU + j];
        float w4 = Wl[(4 * 128 + kk) * UU + j];
        float w5 = Wl[(5 * 128 + kk) * UU + j];
        v = w3 + c * (w4 + w5);
    }
    __nv_bfloat16 hi = __float2bfloat16_rn(v);
    size_t o = (size_t)l * UU * K2 + (size_t)j * K2 + k;
    g_bhi[o] = hi;
    g_blo[o] = __float2bfloat16_rn(v - __bfloat162float(hi));
}

__global__ void fold_bn_kernel(const float* __restrict__ gamma, const float* __restrict__ beta,
                               const float* __restrict__ mm, const float* __restrict__ mv) {
    int t = blockIdx.x * blockDim.x + threadIdx.x;
    if (t >= DEPTH * UU) return;
    float a = gamma[t] * rsqrtf(mv[t] + 1e-3f);
    g_bn_a[t] = a;
    g_bn_d[t] = beta[t] - mm[t] * a;
}

// ------------------- aggregation: one warp per node, emits bf16 split -------------------
__global__ void agg_kernel(const float* __restrict__ xin, const int* __restrict__ ei) {
    const float* x = xin ? xin : g_x;
    int gw = (blockIdx.x * blockDim.x + threadIdx.x) >> 5;
    int lane = threadIdx.x & 31;
    if (gw >= MM) return;
    int b = gw >> 12;
    int nd = gw & (NN - 1);
    const int* ep = ei + 2 * ((size_t)b * EE + (size_t)nd * DEG);
    int myd = (lane < DEG) ? ep[2 * lane + 1] : 0;
    const float* xb = x + (size_t)b * NN * UU;
    float4 s = make_float4(0.f, 0.f, 0.f, 0.f);
    float ninf = __int_as_float(0xff800000);
    float4 mx = make_float4(ninf, ninf, ninf, ninf);
    #pragma unroll
    for (int e = 0; e < DEG; e++) {
        int d = __shfl_sync(0xffffffffu, myd, e);
        float4 v = __ldg((const float4*)(xb + (size_t)d * UU + lane * 4));
        s.x += v.x; s.y += v.y; s.z += v.z; s.w += v.w;
        mx.x = fmaxf(mx.x, v.x); mx.y = fmaxf(mx.y, v.y);
        mx.z = fmaxf(mx.z, v.z); mx.w = fmaxf(mx.w, v.w);
    }
    float vv[8] = {s.x, s.y, s.z, s.w, mx.x, mx.y, mx.z, mx.w};
    uint32_t hs[8], ls[8];
    #pragma unroll
    for (int q = 0; q < 8; q++) {
        __nv_bfloat16 hi = __float2bfloat16_rn(vv[q]);
        hs[q] = (uint32_t)__bfloat16_as_ushort(hi);
        ls[q] = (uint32_t)__bfloat16_as_ushort(__float2bfloat16_rn(vv[q] - __bfloat162float(hi)));
    }
    char* ph = (char*)(g_ahi + (size_t)gw * K2 + lane * 4);
    char* pl = (char*)(g_alo + (size_t)gw * K2 + lane * 4);
    uint2 u;
    u.x = hs[0] | (hs[1] << 16); u.y = hs[2] | (hs[3] << 16);
    *(uint2*)ph = u;
    u.x = hs[4] | (hs[5] << 16); u.y = hs[6] | (hs[7] << 16);
    *(uint2*)(ph + 128 * 2) = u;
    u.x = ls[0] | (ls[1] << 16); u.y = ls[2] | (ls[3] << 16);
    *(uint2*)pl = u;
    u.x = ls[4] | (ls[5] << 16); u.y = ls[6] | (ls[7] << 16);
    *(uint2*)(pl + 128 * 2) = u;
}

// ------------------- bf16-split GEMM via mma.sync + fused epilogue -------------------
// C[m][n] = relu(sum_k A[m][k]*B[n][k] + bias[n]) * av[n] + dv[n]
// Per CTA: 256 output rows (two 128-row tiles), N=128 full, K=256 in 4 chunks of 64.
// smem: A hi/lo double-buffered chunks, B hi/lo fully resident.
#define SA_HI 0
#define SA_LO (2*16384)
#define SB_HI (4*16384)
#define SB_LO (8*16384)
#define S_EPI (12*16384)
#define GEMM_SMEM (12*16384 + 3*128*4)

__global__ __launch_bounds__(256) void gemm_epi_kernel(int l, const float* __restrict__ bias) {
    extern __shared__ __align__(1024) char smem[];
    uint32_t sb = smem_u32(smem);
    int tid = threadIdx.x, lane = tid & 31, wid = tid >> 5;
    int warp_m = wid & 3, warp_n = wid >> 2;
    const __nv_bfloat16* Bh = g_bhi + (size_t)l * UU * K2;
    const __nv_bfloat16* Bl = g_blo + (size_t)l * UU * K2;
    float* sepi = (float*)(smem + S_EPI);
    if (tid < 128) {
        sepi[tid]       = __ldg(bias + tid);
        sepi[128 + tid] = g_bn_a[l * UU + tid];
        sepi[256 + tid] = g_bn_d[l * UU + tid];
    }

    // ---- stage all of B (hi+lo, 4 chunk-tiles each) ----
    #pragma unroll
    for (int t = 0; t < 32; t++) {
        int q = tid + t * 256;          // 0..8191
        int arr = q >> 12;              // 0 hi, 1 lo
        int rem = q & 4095;
        int ch = rem >> 10;
        int seg = rem & 1023;
        int row = seg >> 3, s = seg & 7;
        uint32_t dst = sb + (arr ? SB_LO : SB_HI) + ch * 16384 + SWZ((uint32_t)(row * 128 + s * 16));
        const char* src = (const char*)(arr ? Bl : Bh) + (size_t)row * 512 + ch * 128 + s * 16;
        cp16(dst, src);
    }
    // ---- A chunk loader: global chunk g (0..7): tile g>>2, k-chunk g&3, stage g&1 ----
    auto loadA = [&](int g) {
        int tt = g >> 2, c = g & 3, st = g & 1;
        int m0 = blockIdx.x * 256 + tt * 128;
        #pragma unroll
        for (int t = 0; t < 8; t++) {
            int q = tid + t * 256;      // 0..2047
            int arr = q >> 10;
            int seg = q & 1023;
            int row = seg >> 3, s = seg & 7;
            uint32_t dst = sb + (arr ? SA_LO : SA_HI) + st * 16384 + SWZ((uint32_t)(row * 128 + s * 16));
            const char* src = (const char*)(arr ? g_alo : g_ahi)
                              + ((size_t)(m0 + row) * 256 + c * 64 + s * 8) * 2;
            cp16(dst, src);
        }
    };
    loadA(0); cp_commit();   // group0 = B + A0
    loadA(1); cp_commit();   // group1 = A1

    // ---- per-lane ldmatrix addresses (swizzled) ----
    int lrA = lane & 15;
    uint32_t kaA = (uint32_t)((lane >> 4) * 16);
    uint32_t a_off[2], a_xor[2];
    #pragma unroll
    for (int i = 0; i < 2; i++) {
        int r = warp_m * 32 + i * 16 + lrA;
        a_off[i] = (uint32_t)(r * 128);
        a_xor[i] = (a_off[i] >> 3) & 0x70;
    }
    int lnB = (lane & 7) + ((lane >> 4) << 3);
    uint32_t kaB = (uint32_t)(((lane >> 3) & 1) * 16);
    uint32_t b_off[4], b_xor[4];
    #pragma unroll
    for (int p = 0; p < 4; p++) {
        int n = warp_n * 64 + p * 16 + lnB;
        b_off[p] = (uint32_t)(n * 128);
        b_xor[p] = (b_off[p] >> 3) & 0x70;
    }

    float acc[2][8][4];
    #pragma unroll
    for (int i = 0; i < 2; i++)
        #pragma unroll
        for (int j = 0; j < 8; j++)
            #pragma unroll
            for (int q = 0; q < 4; q++) acc[i][j][q] = 0.f;

    #pragma unroll 1
    for (int g = 0; g < 8; g++) {
        if (g < 7) asm volatile("cp.async.wait_group 1;" ::: "memory");
        else       asm volatile("cp.async.wait_group 0;" ::: "memory");
        __syncthreads();
        int st = g & 1, ch = g & 3;
        uint32_t Ah = sb + SA_HI + st * 16384;
        uint32_t Al = sb + SA_LO + st * 16384;
        uint32_t Bhs = sb + SB_HI + ch * 16384;
        uint32_t Bls = sb + SB_LO + ch * 16384;
        #pragma unroll
        for (int ks = 0; ks < 4; ks++) {
            uint32_t kb = (uint32_t)(ks * 32);
            uint32_t ahi[2][4], alo[2][4], bhi[4][4], blo[4][4];
            #pragma unroll
            for (int i = 0; i < 2; i++) {
                ldmx4(ahi[i], Ah + a_off[i] + ((kb + kaA) ^ a_xor[i]));
                ldmx4(alo[i], Al + a_off[i] + ((kb + kaA) ^ a_xor[i]));
            }
            #pragma unroll
            for (int p = 0; p < 4; p++) {
                ldmx4(bhi[p], Bhs + b_off[p] + ((kb + kaB) ^ b_xor[p]));
                ldmx4(blo[p], Bls + b_off[p] + ((kb + kaB) ^ b_xor[p]));
            }
            #pragma unroll
            for (int i = 0; i < 2; i++)
                #pragma unroll
                for (int j = 0; j < 8; j++) {
                    int p = j >> 1, s2 = (j & 1) * 2;
                    mma_bf16(acc[i][j], ahi[i], bhi[p][s2], bhi[p][s2 + 1]);
                    mma_bf16(acc[i][j], ahi[i], blo[p][s2], blo[p][s2 + 1]);
                    mma_bf16(acc[i][j], alo[i], bhi[p][s2], bhi[p][s2 + 1]);
                }
        }
        if ((g & 3) == 3) {
            // epilogue for tile (g>>2)
            int mbase = blockIdx.x * 256 + (g >> 2) * 128 + warp_m * 32 + (lane >> 2);
            #pragma unroll
            for (int i = 0; i < 2; i++)
                #pragma unroll
                for (int j = 0; j < 8; j++) {
                    int col = warp_n * 64 + j * 8 + (lane & 3) * 2;
                    float b0 = sepi[col], b1 = sepi[col + 1];
                    float a0 = sepi[128 + col], a1 = sepi[128 + col + 1];
                    float d0 = sepi[256 + col], d1 = sepi[256 + col + 1];
                    int r0 = mbase + i * 16;
                    float2 o;
                    o.x = fmaxf(acc[i][j][0] + b0, 0.f) * a0 + d0;
                    o.y = fmaxf(acc[i][j][1] + b1, 0.f) * a1 + d1;
                    *(float2*)&g_x[(size_t)r0 * UU + col] = o;
                    o.x = fmaxf(acc[i][j][2] + b0, 0.f) * a0 + d0;
                    o.y = fmaxf(acc[i][j][3] + b1, 0.f) * a1 + d1;
                    *(float2*)&g_x[(size_t)(r0 + 8) * UU + col] = o;
                    acc[i][j][0] = acc[i][j][1] = acc[i][j][2] = acc[i][j][3] = 0.f;
                }
        }
        __syncthreads();
        if (g + 2 < 8) { loadA(g + 2); cp_commit(); }
    }
}

// ------------------- readout + MLP -------------------
__global__ void readout_kernel() {
    int b = blockIdx.x, j = threadIdx.x;
    const float* xb = g_x + (size_t)b * NN * UU;
    float s0 = 0.f, s1 = 0.f, s2 = 0.f, s3 = 0.f;
    for (int n = 0; n < NN; n += 4) {
        s0 += xb[(size_t)n * UU + j];
        s1 += xb[(size_t)(n + 1) * UU + j];
        s2 += xb[(size_t)(n + 2) * UU + j];
        s3 += xb[(size_t)(n + 3) * UU + j];
    }
    g_gm[b * UU + j] = (s0 + s1 + s2 + s3) * (1.f / NN);
}

__global__ void mlp1_kernel(const float* __restrict__ Wp1, const float* __restrict__ bp1) {
    __shared__ float gs[UU];
    int b = blockIdx.x, j = threadIdx.x;
    gs[j] = g_gm[b * UU + j];
    __syncthreads();
    float acc = bp1[j];
    #pragma unroll 8
    for (int k = 0; k < UU; k++) acc += gs[k] * Wp1[k * UU + j];
    g_h1[b * UU + j] = fmaxf(acc, 0.f);
}

__global__ void mlp2_kernel(const float* __restrict__ Wp2, const float* __restrict__ bp2,
                            float* __restrict__ out) {
    __shared__ float gs[UU];
    int b = blockIdx.x, j = threadIdx.x;  // 64 threads
    gs[j] = g_h1[b * UU + j];
    gs[j + 64] = g_h1[b * UU + j + 64];
    __syncthreads();
    float acc = bp2[j];
    #pragma unroll 8
    for (int k = 0; k < UU; k++) acc += gs[k] * Wp2[k * 64 + j];
    out[b * 64 + j] = fmaxf(acc, 0.f);
}

// ------------------- launch -------------------
extern "C" void kernel_launch(void* const* d_in, const int* in_sizes, int n_in,
                              void* d_out, int out_size) {
    const float* x0    = (const float*)d_in[0];
    const int*   ei    = (const int*)d_in[1];
    const float* W     = (const float*)d_in[2];
    const float* bvec  = (const float*)d_in[3];
    const float* gamma = (const float*)d_in[4];
    const float* beta  = (const float*)d_in[5];
    const float* mmean = (const float*)d_in[6];
    const float* mvar  = (const float*)d_in[7];
    const float* Wp1   = (const float*)d_in[8];
    const float* bp1   = (const float*)d_in[9];
    const float* Wp2   = (const float*)d_in[10];
    const float* bp2   = (const float*)d_in[11];

    cudaFuncSetAttribute(gemm_epi_kernel, cudaFuncAttributeMaxDynamicSharedMemorySize, GEMM_SMEM);

    fold_w_kernel<<<96, 1024>>>(W);
    fold_bn_kernel<<<3, 128>>>(gamma, beta, mmean, mvar);

    for (int l = 0; l < DEPTH; l++) {
        agg_kernel<<<MM / 8, 256>>>(l == 0 ? x0 : (const float*)nullptr, ei);
        gemm_epi_kernel<<<MM / 256, 256, GEMM_SMEM>>>(l, bvec + l * UU);
    }

    readout_kernel<<<BB, 128>>>();
    mlp1_kernel<<<BB, 128>>>(Wp1, bp1);
    mlp2_kernel<<<BB, 64>>>(Wp2, bp2, (float*)d_out);
}

// round 5
// speedup vs baseline: 2.3391x; 1.3909x over previous
#include <cuda_runtime.h>
#include <cuda_bf16.h>
#include <math.h>
#include <stdint.h>

#define BB 8
#define NN 4096
#define DEG 16
#define UU 128
#define EE (NN*DEG)
#define MM (BB*NN)
#define K2 256
#define DEPTH 3
#define SCALE_C 1.2304489f

// ------------------- device scratch (ping-pong feature buffers) -------------------
__device__ float g_xa[(size_t)MM * UU];
__device__ float g_xb[(size_t)MM * UU];
__device__ __nv_bfloat16 g_bhi[DEPTH * UU * K2];       // folded W, [n][k] K-major, hi
__device__ __nv_bfloat16 g_blo[DEPTH * UU * K2];
__device__ float g_bn_a[DEPTH * UU];
__device__ float g_bn_d[DEPTH * UU];
__device__ float g_gm[BB * UU];
__device__ float g_h1[BB * UU];

// ------------------- helpers -------------------
__device__ __forceinline__ uint32_t smem_u32(const void* p) {
    uint32_t a;
    asm("{ .reg .u64 t; cvta.to.shared.u64 t, %1; cvt.u32.u64 %0, t; }" : "=r"(a) : "l"(p));
    return a;
}
__device__ __forceinline__ void cp16(uint32_t dst, const void* src) {
    asm volatile("cp.async.cg.shared.global [%0], [%1], 16;" :: "r"(dst), "l"(src) : "memory");
}
__device__ __forceinline__ void ldmx4(uint32_t* r, uint32_t addr) {
    asm volatile("ldmatrix.sync.aligned.m8n8.x4.shared.b16 {%0,%1,%2,%3}, [%4];"
                 : "=r"(r[0]), "=r"(r[1]), "=r"(r[2]), "=r"(r[3]) : "r"(addr));
}
__device__ __forceinline__ void mma_bf16(float* c, const uint32_t* a, uint32_t b0, uint32_t b1) {
    asm volatile("mma.sync.aligned.m16n8k16.row.col.f32.bf16.bf16.f32 "
                 "{%0,%1,%2,%3}, {%4,%5,%6,%7}, {%8,%9}, {%0,%1,%2,%3};"
                 : "+f"(c[0]), "+f"(c[1]), "+f"(c[2]), "+f"(c[3])
                 : "r"(a[0]), "r"(a[1]), "r"(a[2]), "r"(a[3]), "r"(b0), "r"(b1));
}
#define SWZ(off) ((off) ^ (((off) >> 3) & 0x70))

// ------------------- weight folding (bf16 split, K-major [n][k]) -------------------
__global__ void fold_w_kernel(const float* __restrict__ W) {
    int t = blockIdx.x * blockDim.x + threadIdx.x;
    if (t >= DEPTH * K2 * UU) return;
    int j = t & 127;          // output feature n
    int k = (t >> 7) & 255;   // k index
    int l = t >> 15;
    const float c = SCALE_C;
    const float* Wl = W + (size_t)l * 1152 * UU;
    float v;
    if (k < 128) {
        float w0 = Wl[(0 * 128 + k) * UU + j];
        float w1 = Wl[(1 * 128 + k) * UU + j];
        float w2 = Wl[(2 * 128 + k) * UU + j];
        float w6 = Wl[(6 * 128 + k) * UU + j];
        float w7 = Wl[(7 * 128 + k) * UU + j];
        float w8 = Wl[(8 * 128 + k) * UU + j];
        v = (w0 + c * (w1 + w2)) * 0.0625f + w6 + c * (w7 + w8);
    } else {
        int kk = k - 128;
        float w3 = Wl[(3 * 128 + kk) * UU + j];
        float w4 = Wl[(4 * 128 + kk) * UU + j];
        float w5 = Wl[(5 * 128 + kk) * UU + j];
        v = w3 + c * (w4 + w5);
    }
    __nv_bfloat16 hi = __float2bfloat16_rn(v);
    size_t o = (size_t)l * UU * K2 + (size_t)j * K2 + k;
    g_bhi[o] = hi;
    g_blo[o] = __float2bfloat16_rn(v - __bfloat162float(hi));
}

// also zeroes g_gm for the readout accumulation
__global__ void fold_bn_kernel(const float* __restrict__ gamma, const float* __restrict__ beta,
                               const float* __restrict__ mm, const float* __restrict__ mv) {
    int t = blockIdx.x * blockDim.x + threadIdx.x;
    if (t < BB * UU) g_gm[t] = 0.f;
    if (t >= DEPTH * UU) return;
    float a = gamma[t] * rsqrtf(mv[t] + 1e-3f);
    g_bn_a[t] = a;
    g_bn_d[t] = beta[t] - mm[t] * a;
}

// ------------------- fused layer kernel: agg + bf16-split + GEMM + BN epilogue -------------------
// Per CTA: M=64 nodes, N=128 outputs, K=256 ([ssum|smax]).
// Reads xin, writes xout (distinct buffers -> no cross-CTA race).
#define SB_HI 0
#define SB_LO 65536
#define SA_HI 131072
#define SA_LO (131072 + 32768)
#define S_EPI (131072 + 65536)
#define FUSED_SMEM (S_EPI + 3*128*4)

__global__ __launch_bounds__(256, 1) void fused_layer_kernel(
        int l, const float* __restrict__ xin, float* __restrict__ xout,
        const int* __restrict__ ei, const float* __restrict__ bias) {
    extern __shared__ __align__(1024) char smem[];
    uint32_t sb = smem_u32(smem);
    int tid = threadIdx.x, lane = tid & 31, wid = tid >> 5;

    // ---- stage B (hi+lo = 128KB) via cp.async; overlaps with the gather below ----
    const __nv_bfloat16* Bh = g_bhi + (size_t)l * UU * K2;
    const __nv_bfloat16* Bl = g_blo + (size_t)l * UU * K2;
    #pragma unroll
    for (int t = 0; t < 32; t++) {
        int q = tid + t * 256;          // 0..8191
        int arr = q >> 12;              // 0 hi, 1 lo
        int rem = q & 4095;
        int ch = rem >> 10;
        int seg = rem & 1023;           // 128 rows x 8 f16x8-segments
        int row = seg >> 3, s = seg & 7;
        uint32_t dst = sb + (arr ? SB_LO : SB_HI) + ch * 16384 + SWZ((uint32_t)(row * 128 + s * 16));
        const char* src = (const char*)(arr ? Bl : Bh) + (size_t)row * 512 + ch * 128 + s * 16;
        cp16(dst, src);
    }
    asm volatile("cp.async.commit_group;" ::: "memory");

    // ---- epilogue params ----
    float* sepi = (float*)(smem + S_EPI);
    if (tid < 128) {
        sepi[tid]       = __ldg(bias + tid);
        sepi[128 + tid] = g_bn_a[l * UU + tid];
        sepi[256 + tid] = g_bn_d[l * UU + tid];
    }

    // ---- aggregation: each warp handles 8 nodes; lane owns cols 4*lane..4*lane+3 ----
    int node0 = blockIdx.x * 64;
    int b = node0 >> 12;
    int nd0 = node0 & (NN - 1);
    const float* xb = xin + (size_t)b * NN * UU;
    const float ninf = __int_as_float(0xff800000);

    uint32_t csum = (uint32_t)(lane >> 4) * 8192;
    uint32_t cmax = csum + 2 * 8192;
    uint32_t cb   = (uint32_t)(lane & 15) * 8;

    #pragma unroll 1
    for (int i = 0; i < 8; i++) {
        int r = wid * 8 + i;            // local node row 0..63
        const int* ep = ei + 2 * ((size_t)b * EE + (size_t)(nd0 + r) * DEG);
        int myd = (lane < DEG) ? ep[2 * lane + 1] : 0;
        float4 s = make_float4(0.f, 0.f, 0.f, 0.f);
        float4 mx = make_float4(ninf, ninf, ninf, ninf);
        #pragma unroll
        for (int e = 0; e < DEG; e++) {
            int d = __shfl_sync(0xffffffffu, myd, e);
            float4 v = __ldg((const float4*)(xb + (size_t)d * UU + lane * 4));
            s.x += v.x; s.y += v.y; s.z += v.z; s.w += v.w;
            mx.x = fmaxf(mx.x, v.x); mx.y = fmaxf(mx.y, v.y);
            mx.z = fmaxf(mx.z, v.z); mx.w = fmaxf(mx.w, v.w);
        }
        float sv[4] = {s.x, s.y, s.z, s.w};
        float mv[4] = {mx.x, mx.y, mx.z, mx.w};
        uint32_t sh[4], sl[4], mh[4], ml[4];
        #pragma unroll
        for (int q = 0; q < 4; q++) {
            __nv_bfloat16 h1 = __float2bfloat16_rn(sv[q]);
            sh[q] = (uint32_t)__bfloat16_as_ushort(h1);
            sl[q] = (uint32_t)__bfloat16_as_ushort(__float2bfloat16_rn(sv[q] - __bfloat162float(h1)));
            __nv_bfloat16 h2 = __float2bfloat16_rn(mv[q]);
            mh[q] = (uint32_t)__bfloat16_as_ushort(h2);
            ml[q] = (uint32_t)__bfloat16_as_ushort(__float2bfloat16_rn(mv[q] - __bfloat162float(h2)));
        }
        uint32_t rowoff = (uint32_t)(r * 128) + (cb ^ (uint32_t)((r & 7) << 4));
        uint2 u;
        u.x = sh[0] | (sh[1] << 16); u.y = sh[2] | (sh[3] << 16);
        *(uint2*)(smem + SA_HI + csum + rowoff) = u;
        u.x = sl[0] | (sl[1] << 16); u.y = sl[2] | (sl[3] << 16);
        *(uint2*)(smem + SA_LO + csum + rowoff) = u;
        u.x = mh[0] | (mh[1] << 16); u.y = mh[2] | (mh[3] << 16);
        *(uint2*)(smem + SA_HI + cmax + rowoff) = u;
        u.x = ml[0] | (ml[1] << 16); u.y = ml[2] | (ml[3] << 16);
        *(uint2*)(smem + SA_LO + cmax + rowoff) = u;
    }

    asm volatile("cp.async.wait_group 0;" ::: "memory");
    __syncthreads();

    // ---- MMA: warp tile 32 rows x 32 cols; warp_m in {0,1}, warp_n in {0..3} ----
    int warp_m = wid & 1, warp_n = wid >> 1;

    int lrA = lane & 15;
    uint32_t kaA = (uint32_t)((lane >> 4) * 16);
    uint32_t a_off[2], a_xor[2];
    #pragma unroll
    for (int i = 0; i < 2; i++) {
        int r = warp_m * 32 + i * 16 + lrA;
        a_off[i] = (uint32_t)(r * 128);
        a_xor[i] = (a_off[i] >> 3) & 0x70;
    }
    int lnB = (lane & 7) + ((lane >> 4) << 3);
    uint32_t kaB = (uint32_t)(((lane >> 3) & 1) * 16);
    uint32_t b_off[2], b_xor[2];
    #pragma unroll
    for (int p = 0; p < 2; p++) {
        int n = warp_n * 32 + p * 16 + lnB;
        b_off[p] = (uint32_t)(n * 128);
        b_xor[p] = (b_off[p] >> 3) & 0x70;
    }

    float acc[2][4][4];
    #pragma unroll
    for (int i = 0; i < 2; i++)
        #pragma unroll
        for (int j = 0; j < 4; j++)
            #pragma unroll
            for (int q = 0; q < 4; q++) acc[i][j][q] = 0.f;

    #pragma unroll
    for (int ch = 0; ch < 4; ch++) {
        uint32_t Ah  = sb + SA_HI + ch * 8192;
        uint32_t Al  = sb + SA_LO + ch * 8192;
        uint32_t Bhs = sb + SB_HI + ch * 16384;
        uint32_t Bls = sb + SB_LO + ch * 16384;
        #pragma unroll
        for (int ks = 0; ks < 4; ks++) {
            uint32_t kb = (uint32_t)(ks * 32);
            uint32_t ahi[2][4], alo[2][4], bhi[2][4], blo[2][4];
            #pragma unroll
            for (int i = 0; i < 2; i++) {
                ldmx4(ahi[i], Ah + a_off[i] + ((kb + kaA) ^ a_xor[i]));
                ldmx4(alo[i], Al + a_off[i] + ((kb + kaA) ^ a_xor[i]));
            }
            #pragma unroll
            for (int p = 0; p < 2; p++) {
                ldmx4(bhi[p], Bhs + b_off[p] + ((kb + kaB) ^ b_xor[p]));
                ldmx4(blo[p], Bls + b_off[p] + ((kb + kaB) ^ b_xor[p]));
            }
            #pragma unroll
            for (int i = 0; i < 2; i++)
                #pragma unroll
                for (int j = 0; j < 4; j++) {
                    int p = j >> 1, s2 = (j & 1) * 2;
                    mma_bf16(acc[i][j], ahi[i], bhi[p][s2], bhi[p][s2 + 1]);
                    mma_bf16(acc[i][j], ahi[i], blo[p][s2], blo[p][s2 + 1]);
                    mma_bf16(acc[i][j], alo[i], bhi[p][s2], bhi[p][s2 + 1]);
                }
        }
    }

    // ---- epilogue ----
    int mbase = node0 + warp_m * 32 + (lane >> 2);
    #pragma unroll
    for (int i = 0; i < 2; i++)
        #pragma unroll
        for (int j = 0; j < 4; j++) {
            int col = warp_n * 32 + j * 8 + (lane & 3) * 2;
            float b0 = sepi[col], b1 = sepi[col + 1];
            float a0 = sepi[128 + col], a1 = sepi[128 + col + 1];
            float d0 = sepi[256 + col], d1 = sepi[256 + col + 1];
            int r0 = mbase + i * 16;
            float2 o;
            o.x = fmaxf(acc[i][j][0] + b0, 0.f) * a0 + d0;
            o.y = fmaxf(acc[i][j][1] + b1, 0.f) * a1 + d1;
            *(float2*)&xout[(size_t)r0 * UU + col] = o;
            o.x = fmaxf(acc[i][j][2] + b0, 0.f) * a0 + d0;
            o.y = fmaxf(acc[i][j][3] + b1, 0.f) * a1 + d1;
            *(float2*)&xout[(size_t)(r0 + 8) * UU + col] = o;
        }
}

// ------------------- readout (parallel partial sums + atomicAdd) -------------------
__global__ void readout_kernel(const float* __restrict__ xin) {
    int b = blockIdx.x >> 4;
    int chunk = blockIdx.x & 15;
    int j = threadIdx.x;
    const float* xb = xin + (size_t)b * NN * UU + (size_t)chunk * 256 * UU;
    float s0 = 0.f, s1 = 0.f, s2 = 0.f, s3 = 0.f;
    for (int n = 0; n < 256; n += 4) {
        s0 += xb[(size_t)n * UU + j];
        s1 += xb[(size_t)(n + 1) * UU + j];
        s2 += xb[(size_t)(n + 2) * UU + j];
        s3 += xb[(size_t)(n + 3) * UU + j];
    }
    atomicAdd(&g_gm[b * UU + j], (s0 + s1 + s2 + s3) * (1.f / NN));
}

__global__ void mlp1_kernel(const float* __restrict__ Wp1, const float* __restrict__ bp1) {
    __shared__ float gs[UU];
    int b = blockIdx.x, j = threadIdx.x;
    gs[j] = g_gm[b * UU + j];
    __syncthreads();
    float acc = bp1[j];
    #pragma unroll 8
    for (int k = 0; k < UU; k++) acc += gs[k] * Wp1[k * UU + j];
    g_h1[b * UU + j] = fmaxf(acc, 0.f);
}

__global__ void mlp2_kernel(const float* __restrict__ Wp2, const float* __restrict__ bp2,
                            float* __restrict__ out) {
    __shared__ float gs[UU];
    int b = blockIdx.x, j = threadIdx.x;  // 64 threads
    gs[j] = g_h1[b * UU + j];
    gs[j + 64] = g_h1[b * UU + j + 64];
    __syncthreads();
    float acc = bp2[j];
    #pragma unroll 8
    for (int k = 0; k < UU; k++) acc += gs[k] * Wp2[k * 64 + j];
    out[b * 64 + j] = fmaxf(acc, 0.f);
}

// ------------------- launch -------------------
extern "C" void kernel_launch(void* const* d_in, const int* in_sizes, int n_in,
                              void* d_out, int out_size) {
    const float* x0    = (const float*)d_in[0];
    const int*   ei    = (const int*)d_in[1];
    const float* W     = (const float*)d_in[2];
    const float* bvec  = (const float*)d_in[3];
    const float* gamma = (const float*)d_in[4];
    const float* beta  = (const float*)d_in[5];
    const float* mmean = (const float*)d_in[6];
    const float* mvar  = (const float*)d_in[7];
    const float* Wp1   = (const float*)d_in[8];
    const float* bp1   = (const float*)d_in[9];
    const float* Wp2   = (const float*)d_in[10];
    const float* bp2   = (const float*)d_in[11];

    cudaFuncSetAttribute(fused_layer_kernel, cudaFuncAttributeMaxDynamicSharedMemorySize, FUSED_SMEM);

    fold_w_kernel<<<96, 1024>>>(W);
    fold_bn_kernel<<<3, 1024>>>(gamma, beta, mmean, mvar);

    float *xa, *xb;
    cudaGetSymbolAddress((void**)&xa, g_xa);
    cudaGetSymbolAddress((void**)&xb, g_xb);

    // l0: x0 -> xa,  l1: xa -> xb,  l2: xb -> xa
    fused_layer_kernel<<<MM / 64, 256, FUSED_SMEM>>>(0, x0, xa, ei, bvec + 0 * UU);
    fused_layer_kernel<<<MM / 64, 256, FUSED_SMEM>>>(1, xa, xb, ei, bvec + 1 * UU);
    fused_layer_kernel<<<MM / 64, 256, FUSED_SMEM>>>(2, xb, xa, ei, bvec + 2 * UU);

    readout_kernel<<<BB * 16, 128>>>(xa);
    mlp1_kernel<<<BB, 128>>>(Wp1, bp1);
    mlp2_kernel<<<BB, 64>>>(Wp2, bp2, (float*)d_out);
}